// round 3
// baseline (speedup 1.0000x reference)
#include <cuda_runtime.h>
#include <math.h>

// ---------------------------------------------------------------------------
// Problem constants
// ---------------------------------------------------------------------------
#define BATCH 32
#define CDIM  256
#define NHEAD 8
#define HDIM  32
#define NW    64          /* windows per batch */
#define NWIN  2048        /* BATCH*NW */
#define NTOK  50          /* 1 cls + 49 patch */
#define HIDD  1024
#define HIMG  56
#define WIMG  56

#define TOK_TOTAL    ((size_t)NWIN * NTOK)                  /* 102400 */
#define CLS_OUT_SZ   ((size_t)BATCH * CDIM * NW)            /* 524288  */
#define PATCH_OUT_SZ ((size_t)BATCH * CDIM * HIMG * WIMG)   /* 25690112 */

// ---------------------------------------------------------------------------
// Scratch pool (single device global, lifetime-based aliasing). 839 MB.
//   X    [26,214,400]  raw tokens (also final MLP residual source)
//   XLN  [26,214,400]  LN output; ALSO attention output; ALSO final tokens F
//   QKV  [78,643,200]  qkv activations; cls-phase buffers alias at its start
//   TMP  [26,214,400]  post-attention residual stream
//   H    [52,428,800]  MLP hidden, one 512-wide chunk at a time
// ---------------------------------------------------------------------------
#define X_OFF    ((size_t)0)
#define XLN_OFF  ((size_t)26214400)
#define QKV_OFF  ((size_t)52428800)
#define TMP_OFF  ((size_t)131072000)
#define H_OFF    ((size_t)157286400)
#define POOL_SZ  ((size_t)209715200)
__device__ __align__(128) float g_pool[POOL_SZ];

// cls-phase aliases (inside QKV region, consumed before QKV gemm runs)
#define CLSFLAT_OFF (QKV_OFF + 0)
#define CLSLN_OFF   (QKV_OFF + 524288)
#define CLSQKV_OFF  (QKV_OFF + 1048576)
#define CLSATT_OFF  (QKV_OFF + 2621440)

// ---------------------------------------------------------------------------
// LayerNorm helpers (256 threads = one row of C=256)
// ---------------------------------------------------------------------------
__device__ __forceinline__ void ln_stats(float v, float& mu, float& inv) {
    float s = v, sq = v * v;
    #pragma unroll
    for (int o = 16; o; o >>= 1) {
        s  += __shfl_xor_sync(0xffffffffu, s,  o);
        sq += __shfl_xor_sync(0xffffffffu, sq, o);
    }
    __shared__ float ss[8], sqs[8];
    int lane = threadIdx.x & 31, wp = threadIdx.x >> 5;
    if (lane == 0) { ss[wp] = s; sqs[wp] = sq; }
    __syncthreads();
    float ts = 0.f, tq = 0.f;
    #pragma unroll
    for (int i = 0; i < 8; i++) { ts += ss[i]; tq += sqs[i]; }
    mu = ts * (1.0f / 256.0f);
    float var = tq * (1.0f / 256.0f) - mu * mu;
    inv = rsqrtf(var + 1e-5f);
}

// cls tokens: gather-transpose (B,C,64) -> rows (b*64+w, C); write raw + LN
__global__ void cls_ln_kernel(const float* __restrict__ cls,
                              const float* __restrict__ w,
                              const float* __restrict__ b,
                              float* __restrict__ flat,
                              float* __restrict__ lnout) {
    int row = blockIdx.x;
    int tid = threadIdx.x;
    int bb = row >> 6, wv = row & 63;
    float v = cls[((size_t)bb * CDIM + tid) * NW + wv];
    flat[(size_t)row * CDIM + tid] = v;
    float mu, inv;
    ln_stats(v, mu, inv);
    lnout[(size_t)row * CDIM + tid] = (v - mu) * inv * w[tid] + b[tid];
}

__global__ void ln_kernel(const float* __restrict__ x,
                          const float* __restrict__ w,
                          const float* __restrict__ b,
                          float* __restrict__ y) {
    size_t row = blockIdx.x;
    int tid = threadIdx.x;
    float v = x[row * CDIM + tid];
    float mu, inv;
    ln_stats(v, mu, inv);
    y[row * CDIM + tid] = (v - mu) * inv * w[tid] + b[tid];
}

// ---------------------------------------------------------------------------
// Gather patch tokens into X rows (win*50 + 1 + k)
// ---------------------------------------------------------------------------
__global__ void gather_patch_kernel(const float* __restrict__ patch,
                                    float* __restrict__ X) {
    size_t idx = (size_t)blockIdx.x * 256 + threadIdx.x;
    if (idx >= (size_t)NWIN * 49 * CDIM) return;
    int c = idx & 255;
    size_t r = idx >> 8;
    int k   = (int)(r % 49);
    int win = (int)(r / 49);
    int b = win >> 6, wv = win & 63;
    int wy = wv >> 3, wx = wv & 7;
    int iy = k / 7, ix = k - iy * 7;
    int y = wy * 7 + iy, x = wx * 7 + ix;
    X[((size_t)win * NTOK + 1 + k) * CDIM + c] =
        patch[(((size_t)b * CDIM + c) * HIMG + y) * WIMG + x];
}

// ---------------------------------------------------------------------------
// SGEMM: C[m,n] = sum_k A[m*lda+k] * B[n*ldb+k]   (NT gemm, K-contiguous)
// 128x128 tile, BK=8, 256 threads, 8x8 register tile. M,N multiples of 128,
// K multiple of 8, pointers float4-aligned.
// mode 0: plain
// mode 1: +res[m*N+n] (+bias[n] if bias)
// mode 2: +bias[n] then exact-erf GELU
// ---------------------------------------------------------------------------
__global__ void __launch_bounds__(256, 2) sgemm_nt(
    const float* __restrict__ A, const float* __restrict__ Bw,
    float* __restrict__ Cp,
    const float* __restrict__ bias, const float* __restrict__ res,
    int M, int N, int K, int lda, int ldb, int ldc, int mode)
{
    __shared__ float As[8][128];
    __shared__ float Bs[8][128];
    const int bm = blockIdx.y * 128, bn = blockIdx.x * 128;
    const int tid = threadIdx.x;
    const int tx = tid & 15, ty = tid >> 4;
    const int lrow = tid >> 1;            // 0..127
    const int lcol = (tid & 1) << 2;      // 0 or 4
    const float* Ap = A  + (size_t)(bm + lrow) * lda + lcol;
    const float* Bp = Bw + (size_t)(bn + lrow) * ldb + lcol;
    float acc[8][8] = {};
    for (int k0 = 0; k0 < K; k0 += 8) {
        float4 av = *(const float4*)(Ap + k0);
        float4 bv = *(const float4*)(Bp + k0);
        __syncthreads();
        As[lcol + 0][lrow] = av.x; As[lcol + 1][lrow] = av.y;
        As[lcol + 2][lrow] = av.z; As[lcol + 3][lrow] = av.w;
        Bs[lcol + 0][lrow] = bv.x; Bs[lcol + 1][lrow] = bv.y;
        Bs[lcol + 2][lrow] = bv.z; Bs[lcol + 3][lrow] = bv.w;
        __syncthreads();
        #pragma unroll
        for (int kk = 0; kk < 8; kk++) {
            float a[8], bb[8];
            *(float4*)(a)      = *(const float4*)&As[kk][ty * 8];
            *(float4*)(a + 4)  = *(const float4*)&As[kk][ty * 8 + 4];
            *(float4*)(bb)     = *(const float4*)&Bs[kk][tx * 8];
            *(float4*)(bb + 4) = *(const float4*)&Bs[kk][tx * 8 + 4];
            #pragma unroll
            for (int i = 0; i < 8; i++)
                #pragma unroll
                for (int j = 0; j < 8; j++)
                    acc[i][j] = fmaf(a[i], bb[j], acc[i][j]);
        }
    }
    #pragma unroll
    for (int i = 0; i < 8; i++) {
        int row = bm + ty * 8 + i;
        #pragma unroll
        for (int j = 0; j < 8; j++) {
            int col = bn + tx * 8 + j;
            float v = acc[i][j];
            if (mode == 1) {
                v += res[(size_t)row * N + col];
                if (bias) v += bias[col];
            } else if (mode == 2) {
                v += bias[col];
                v = 0.5f * v * (1.0f + erff(v * 0.70710678118654752f));
            }
            Cp[(size_t)row * ldc + col] = v;
        }
    }
}

// ---------------------------------------------------------------------------
// Attention: one block per (window, head). N tokens, hd=32.
// qkv row layout: [3][8][32]  (q @ h*32, k @ 256+h*32, v @ 512+h*32)
// ---------------------------------------------------------------------------
template<int N, bool BIAS>
__global__ void __launch_bounds__(256) attn_kernel(
    const float* __restrict__ qkv, const float* __restrict__ rel_pos,
    float* __restrict__ out)
{
    __shared__ float Qs[N][33], Ks[N][33], Vs[N][33];
    __shared__ float S[N][N];
    const int head = blockIdx.x & 7;
    const int win  = blockIdx.x >> 3;
    const int tid  = threadIdx.x;
    const float* base = qkv + (size_t)win * N * (3 * CDIM);

    for (int idx = tid; idx < N * HDIM; idx += 256) {
        int t = idx >> 5, d = idx & 31;
        const float* r = base + (size_t)t * 768 + head * 32 + d;
        Qs[t][d] = r[0];
        Ks[t][d] = r[256];
        Vs[t][d] = r[512];
    }
    __syncthreads();

    const float scale = 0.1767766952966369f; // 1/sqrt(32)
    for (int idx = tid; idx < N * N; idx += 256) {
        int i = idx / N, j = idx - i * N;
        float s = 0.f;
        #pragma unroll
        for (int d = 0; d < 32; d++) s = fmaf(Qs[i][d], Ks[j][d], s);
        s *= scale;
        if (BIAS) {
            if (i > 0 && j > 0) {
                int pi = i - 1, pj = j - 1;
                int dy = pi / 7 - pj / 7 + 6;
                int dx = pi % 7 - pj % 7 + 6;
                s += rel_pos[head * 169 + dy * 13 + dx];
            }
        }
        S[i][j] = s;
    }
    __syncthreads();

    int lane = tid & 31, wp = tid >> 5;
    for (int i = wp; i < N; i += 8) {
        float m = -1e30f;
        for (int j = lane; j < N; j += 32) m = fmaxf(m, S[i][j]);
        #pragma unroll
        for (int o = 16; o; o >>= 1) m = fmaxf(m, __shfl_xor_sync(0xffffffffu, m, o));
        float sum = 0.f;
        for (int j = lane; j < N; j += 32) {
            float e = __expf(S[i][j] - m);
            S[i][j] = e;
            sum += e;
        }
        #pragma unroll
        for (int o = 16; o; o >>= 1) sum += __shfl_xor_sync(0xffffffffu, sum, o);
        float inv = 1.0f / sum;
        for (int j = lane; j < N; j += 32) S[i][j] *= inv;
    }
    __syncthreads();

    for (int idx = tid; idx < N * HDIM; idx += 256) {
        int i = idx >> 5, d = idx & 31;
        float o = 0.f;
        for (int j = 0; j < N; j++) o = fmaf(S[i][j], Vs[j][d], o);
        out[((size_t)win * N + i) * CDIM + head * 32 + d] = o;
    }
}

// ---------------------------------------------------------------------------
// Scatter final tokens to (cls_out, patch_out) in NCHW
// ---------------------------------------------------------------------------
__global__ void scatter_out_kernel(const float* __restrict__ F,
                                   float* __restrict__ out) {
    size_t idx = (size_t)blockIdx.x * 256 + threadIdx.x;
    const size_t total = CLS_OUT_SZ + PATCH_OUT_SZ;
    if (idx >= total) return;
    if (idx < CLS_OUT_SZ) {
        int wv = idx & 63;
        int c  = (int)((idx >> 6) & 255);
        int b  = (int)(idx >> 14);
        out[idx] = F[((size_t)(b * 64 + wv) * NTOK) * CDIM + c];
    } else {
        size_t p = idx - CLS_OUT_SZ;
        int x = (int)(p % 56);
        int y = (int)((p / 56) % 56);
        int c = (int)((p / (56 * 56)) & 255);
        int b = (int)(p / ((size_t)56 * 56 * 256));
        int wy = y / 7, iy = y - wy * 7;
        int wx = x / 7, ix = x - wx * 7;
        size_t row = (size_t)(b * 64 + wy * 8 + wx) * NTOK + 1 + iy * 7 + ix;
        out[idx] = F[row * CDIM + c];
    }
}

// ---------------------------------------------------------------------------
// Launch sequence
// ---------------------------------------------------------------------------
extern "C" void kernel_launch(void* const* d_in, const int* in_sizes, int n_in,
                              void* d_out, int out_size)
{
    const float* cls    = (const float*)d_in[0];
    const float* patch  = (const float*)d_in[1];
    const float* n0w = (const float*)d_in[2], *n0b = (const float*)d_in[3];
    const float* n1w = (const float*)d_in[4], *n1b = (const float*)d_in[5];
    const float* n2w = (const float*)d_in[6], *n2b = (const float*)d_in[7];
    const float* qkvw  = (const float*)d_in[8];
    const float* projw = (const float*)d_in[9], *projb = (const float*)d_in[10];
    const float* relp  = (const float*)d_in[11];
    const float* fc1w  = (const float*)d_in[12], *fc1b = (const float*)d_in[13];
    const float* fc2w  = (const float*)d_in[14], *fc2b = (const float*)d_in[15];
    float* out = (float*)d_out;

    float* pool;
    cudaGetSymbolAddress((void**)&pool, g_pool);
    float* X       = pool + X_OFF;
    float* Xln     = pool + XLN_OFF;
    float* QKV     = pool + QKV_OFF;
    float* TMP     = pool + TMP_OFF;
    float* Hb      = pool + H_OFF;
    float* clsflat = pool + CLSFLAT_OFF;
    float* clsln   = pool + CLSLN_OFF;
    float* clsqkv  = pool + CLSQKV_OFF;
    float* clsattn = pool + CLSATT_OFF;
    float* ATT = Xln;   // attention output reuses Xln (dead after QKV gemm)
    float* F   = Xln;   // final tokens reuse Xln (dead after fc1)

    const unsigned MB = (unsigned)(TOK_TOTAL / 128);   // 800

    // ---- cls-token path: LN -> QKV -> MHA(64) -> proj+residual into X row 0
    cls_ln_kernel<<<NWIN, 256>>>(cls, n0w, n0b, clsflat, clsln);
    sgemm_nt<<<dim3(6, 16), 256>>>(clsln, qkvw, clsqkv, nullptr, nullptr,
                                   NWIN, 768, 256, 256, 256, 768, 0);
    attn_kernel<64, false><<<BATCH * NHEAD, 256>>>(clsqkv, nullptr, clsattn);
    sgemm_nt<<<dim3(2, 16), 256>>>(clsattn, projw, X, projb, clsflat,
                                   NWIN, 256, 256, 256, 256, NTOK * CDIM, 1);

    // ---- assemble X (patch rows), windowed attention block
    {
        size_t n = (size_t)NWIN * 49 * CDIM;
        gather_patch_kernel<<<(unsigned)((n + 255) / 256), 256>>>(patch, X);
    }
    ln_kernel<<<(unsigned)TOK_TOTAL, 256>>>(X, n1w, n1b, Xln);
    sgemm_nt<<<dim3(6, MB), 256>>>(Xln, qkvw, QKV, nullptr, nullptr,
                                   (int)TOK_TOTAL, 768, 256, 256, 256, 768, 0);
    attn_kernel<NTOK, true><<<NWIN * NHEAD, 256>>>(QKV, relp, ATT);
    sgemm_nt<<<dim3(2, MB), 256>>>(ATT, projw, TMP, projb, X,
                                   (int)TOK_TOTAL, 256, 256, 256, 256, 256, 1);

    // ---- MLP block: LN2 -> (fc1 chunk -> GELU -> fc2 partial) x2
    ln_kernel<<<(unsigned)TOK_TOTAL, 256>>>(TMP, n2w, n2b, X);  // X reused: dead
    // chunk 0 (hidden cols 0..511)
    sgemm_nt<<<dim3(4, MB), 256>>>(X, fc1w, Hb, fc1b, nullptr,
                                   (int)TOK_TOTAL, 512, 256, 256, 256, 512, 2);
    sgemm_nt<<<dim3(2, MB), 256>>>(Hb, fc2w, F, fc2b, TMP,
                                   (int)TOK_TOTAL, 256, 512, 512, HIDD, 256, 1);
    // chunk 1 (hidden cols 512..1023), accumulate into F
    sgemm_nt<<<dim3(4, MB), 256>>>(X, fc1w + 512 * 256, Hb, fc1b + 512, nullptr,
                                   (int)TOK_TOTAL, 512, 256, 256, 256, 512, 2);
    sgemm_nt<<<dim3(2, MB), 256>>>(Hb, fc2w + 512, F, nullptr, F,
                                   (int)TOK_TOTAL, 256, 512, 512, HIDD, 256, 1);

    // ---- outputs
    {
        size_t n = CLS_OUT_SZ + PATCH_OUT_SZ;
        scatter_out_kernel<<<(unsigned)((n + 255) / 256), 256>>>(F, out);
    }
}

// round 4
// speedup vs baseline: 2.0445x; 2.0445x over previous
#include <cuda_runtime.h>
#include <math.h>
#include <stdint.h>

// ---------------------------------------------------------------------------
// Problem constants
// ---------------------------------------------------------------------------
#define BATCH 32
#define CDIM  256
#define NHEAD 8
#define HDIM  32
#define NW    64
#define NWIN  2048
#define NTOK  50
#define HIDD  1024
#define HIMG  56
#define WIMG  56

#define TOK_TOTAL    ((size_t)NWIN * NTOK)                  /* 102400 */
#define CLS_OUT_SZ   ((size_t)BATCH * CDIM * NW)            /* 524288  */
#define PATCH_OUT_SZ ((size_t)BATCH * CDIM * HIMG * WIMG)   /* 25690112 */

// ---------------------------------------------------------------------------
// Scratch pool (single device global, lifetime-based aliasing). 839 MB.
// ---------------------------------------------------------------------------
#define X_OFF    ((size_t)0)
#define XLN_OFF  ((size_t)26214400)
#define QKV_OFF  ((size_t)52428800)
#define TMP_OFF  ((size_t)131072000)
#define H_OFF    ((size_t)157286400)
#define POOL_SZ  ((size_t)209715200)
__device__ __align__(128) float g_pool[POOL_SZ];

#define CLSFLAT_OFF (QKV_OFF + 0)
#define CLSLN_OFF   (QKV_OFF + 524288)
#define CLSQKV_OFF  (QKV_OFF + 1048576)
#define CLSATT_OFF  (QKV_OFF + 2621440)

// ---------------------------------------------------------------------------
// LayerNorm helpers
// ---------------------------------------------------------------------------
__device__ __forceinline__ void ln_stats(float v, float& mu, float& inv) {
    float s = v, sq = v * v;
    #pragma unroll
    for (int o = 16; o; o >>= 1) {
        s  += __shfl_xor_sync(0xffffffffu, s,  o);
        sq += __shfl_xor_sync(0xffffffffu, sq, o);
    }
    __shared__ float ss[8], sqs[8];
    int lane = threadIdx.x & 31, wp = threadIdx.x >> 5;
    if (lane == 0) { ss[wp] = s; sqs[wp] = sq; }
    __syncthreads();
    float ts = 0.f, tq = 0.f;
    #pragma unroll
    for (int i = 0; i < 8; i++) { ts += ss[i]; tq += sqs[i]; }
    mu = ts * (1.0f / 256.0f);
    float var = tq * (1.0f / 256.0f) - mu * mu;
    inv = rsqrtf(var + 1e-5f);
}

__global__ void cls_ln_kernel(const float* __restrict__ cls,
                              const float* __restrict__ w,
                              const float* __restrict__ b,
                              float* __restrict__ flat,
                              float* __restrict__ lnout) {
    int row = blockIdx.x;
    int tid = threadIdx.x;
    int bb = row >> 6, wv = row & 63;
    float v = cls[((size_t)bb * CDIM + tid) * NW + wv];
    flat[(size_t)row * CDIM + tid] = v;
    float mu, inv;
    ln_stats(v, mu, inv);
    lnout[(size_t)row * CDIM + tid] = (v - mu) * inv * w[tid] + b[tid];
}

__global__ void ln_kernel(const float* __restrict__ x,
                          const float* __restrict__ w,
                          const float* __restrict__ b,
                          float* __restrict__ y) {
    size_t row = blockIdx.x;
    int tid = threadIdx.x;
    float v = x[row * CDIM + tid];
    float mu, inv;
    ln_stats(v, mu, inv);
    y[row * CDIM + tid] = (v - mu) * inv * w[tid] + b[tid];
}

// ---------------------------------------------------------------------------
// Gather patch tokens into X rows (win*50 + 1 + k)
// ---------------------------------------------------------------------------
__global__ void gather_patch_kernel(const float* __restrict__ patch,
                                    float* __restrict__ X) {
    size_t idx = (size_t)blockIdx.x * 256 + threadIdx.x;
    if (idx >= (size_t)NWIN * 49 * CDIM) return;
    int c = idx & 255;
    size_t r = idx >> 8;
    int k   = (int)(r % 49);
    int win = (int)(r / 49);
    int b = win >> 6, wv = win & 63;
    int wy = wv >> 3, wx = wv & 7;
    int iy = k / 7, ix = k - iy * 7;
    int y = wy * 7 + iy, x = wx * 7 + ix;
    X[((size_t)win * NTOK + 1 + k) * CDIM + c] =
        patch[(((size_t)b * CDIM + c) * HIMG + y) * WIMG + x];
}

// ---------------------------------------------------------------------------
// TF32 tensor-core GEMM: C[m,n] = sum_k A[m*lda+k] * B[n*ldb+k]  (NT)
// 128x128 tile, BK=16, 256 threads = 8 warps (2x4), warp tile 64x32,
// mma.sync.aligned.m16n8k8.row.col.f32.tf32.tf32.f32.
// M,N multiples of 128, K multiple of 16, pointers float4-aligned.
// mode 0: plain | mode 1: +res (+bias if non-null) | mode 2: +bias, GELU(erf)
// ---------------------------------------------------------------------------
__device__ __forceinline__ uint32_t f2tf32(float f) {
    uint32_t r;
    asm("cvt.rna.tf32.f32 %0, %1;" : "=r"(r) : "f"(f));
    return r;
}

__global__ void __launch_bounds__(256, 2) tf32gemm_nt(
    const float* __restrict__ A, const float* __restrict__ Bw,
    float* __restrict__ Cp,
    const float* __restrict__ bias, const float* __restrict__ res,
    int M, int N, int K, int lda, int ldb, int ldc, int mode)
{
    __shared__ uint32_t As[128 * 20];
    __shared__ uint32_t Bs[128 * 20];
    const int bm = blockIdx.y * 128, bn = blockIdx.x * 128;
    const int tid  = threadIdx.x;
    const int warp = tid >> 5, lane = tid & 31;
    const int wm = warp >> 2, wn = warp & 3;      // 2 x 4 warp grid
    const int g  = lane >> 2, tg = lane & 3;      // group row / thread-in-group

    float acc[4][4][4];
    #pragma unroll
    for (int i = 0; i < 4; i++)
        #pragma unroll
        for (int j = 0; j < 4; j++)
            #pragma unroll
            for (int r = 0; r < 4; r++) acc[i][j][r] = 0.f;

    const int srow = tid >> 1;            // 0..127
    const int skc  = (tid & 1) * 8;       // 0 or 8
    const float* Ap = A  + (size_t)(bm + srow) * lda + skc;
    const float* Bp = Bw + (size_t)(bn + srow) * ldb + skc;

    for (int k0 = 0; k0 < K; k0 += 16) {
        float4 av0 = *(const float4*)(Ap + k0);
        float4 av1 = *(const float4*)(Ap + k0 + 4);
        float4 bv0 = *(const float4*)(Bp + k0);
        float4 bv1 = *(const float4*)(Bp + k0 + 4);
        __syncthreads();
        uint32_t* as = &As[srow * 20 + skc];
        as[0] = f2tf32(av0.x); as[1] = f2tf32(av0.y);
        as[2] = f2tf32(av0.z); as[3] = f2tf32(av0.w);
        as[4] = f2tf32(av1.x); as[5] = f2tf32(av1.y);
        as[6] = f2tf32(av1.z); as[7] = f2tf32(av1.w);
        uint32_t* bs = &Bs[srow * 20 + skc];
        bs[0] = f2tf32(bv0.x); bs[1] = f2tf32(bv0.y);
        bs[2] = f2tf32(bv0.z); bs[3] = f2tf32(bv0.w);
        bs[4] = f2tf32(bv1.x); bs[5] = f2tf32(bv1.y);
        bs[6] = f2tf32(bv1.z); bs[7] = f2tf32(bv1.w);
        __syncthreads();

        #pragma unroll
        for (int kk = 0; kk < 16; kk += 8) {
            uint32_t af[4][4], bf[4][2];
            #pragma unroll
            for (int mt = 0; mt < 4; mt++) {
                int row = wm * 64 + mt * 16 + g;
                af[mt][0] = As[row * 20 + kk + tg];
                af[mt][1] = As[(row + 8) * 20 + kk + tg];
                af[mt][2] = As[row * 20 + kk + tg + 4];
                af[mt][3] = As[(row + 8) * 20 + kk + tg + 4];
            }
            #pragma unroll
            for (int nt = 0; nt < 4; nt++) {
                int n = wn * 32 + nt * 8 + g;
                bf[nt][0] = Bs[n * 20 + kk + tg];
                bf[nt][1] = Bs[n * 20 + kk + tg + 4];
            }
            #pragma unroll
            for (int mt = 0; mt < 4; mt++)
                #pragma unroll
                for (int nt = 0; nt < 4; nt++) {
                    asm volatile(
                        "mma.sync.aligned.m16n8k8.row.col.f32.tf32.tf32.f32 "
                        "{%0,%1,%2,%3}, {%4,%5,%6,%7}, {%8,%9}, {%0,%1,%2,%3};"
                        : "+f"(acc[mt][nt][0]), "+f"(acc[mt][nt][1]),
                          "+f"(acc[mt][nt][2]), "+f"(acc[mt][nt][3])
                        : "r"(af[mt][0]), "r"(af[mt][1]),
                          "r"(af[mt][2]), "r"(af[mt][3]),
                          "r"(bf[nt][0]), "r"(bf[nt][1]));
                }
        }
    }

    // Epilogue. c0,c1 -> row g, cols 2tg,2tg+1 ; c2,c3 -> row g+8.
    #pragma unroll
    for (int mt = 0; mt < 4; mt++) {
        #pragma unroll
        for (int half = 0; half < 2; half++) {
            int row = bm + wm * 64 + mt * 16 + g + half * 8;
            #pragma unroll
            for (int nt = 0; nt < 4; nt++) {
                int col = bn + wn * 32 + nt * 8 + tg * 2;
                float v0 = acc[mt][nt][half * 2 + 0];
                float v1 = acc[mt][nt][half * 2 + 1];
                if (mode == 1) {
                    const float2 rv = *(const float2*)&res[(size_t)row * N + col];
                    v0 += rv.x; v1 += rv.y;
                    if (bias) { v0 += bias[col]; v1 += bias[col + 1]; }
                } else if (mode == 2) {
                    v0 += bias[col]; v1 += bias[col + 1];
                    v0 = 0.5f * v0 * (1.0f + erff(v0 * 0.70710678118654752f));
                    v1 = 0.5f * v1 * (1.0f + erff(v1 * 0.70710678118654752f));
                }
                *(float2*)&Cp[(size_t)row * ldc + col] = make_float2(v0, v1);
            }
        }
    }
}

// ---------------------------------------------------------------------------
// Attention: one block per (window, head). N tokens, hd=32.
// ---------------------------------------------------------------------------
template<int N, bool BIAS>
__global__ void __launch_bounds__(256) attn_kernel(
    const float* __restrict__ qkv, const float* __restrict__ rel_pos,
    float* __restrict__ out)
{
    __shared__ float Qs[N][33], Ks[N][33], Vs[N][33];
    __shared__ float S[N][N];
    const int head = blockIdx.x & 7;
    const int win  = blockIdx.x >> 3;
    const int tid  = threadIdx.x;
    const float* base = qkv + (size_t)win * N * (3 * CDIM);

    for (int idx = tid; idx < N * HDIM; idx += 256) {
        int t = idx >> 5, d = idx & 31;
        const float* r = base + (size_t)t * 768 + head * 32 + d;
        Qs[t][d] = r[0];
        Ks[t][d] = r[256];
        Vs[t][d] = r[512];
    }
    __syncthreads();

    const float scale = 0.1767766952966369f;
    for (int idx = tid; idx < N * N; idx += 256) {
        int i = idx / N, j = idx - i * N;
        float s = 0.f;
        #pragma unroll
        for (int d = 0; d < 32; d++) s = fmaf(Qs[i][d], Ks[j][d], s);
        s *= scale;
        if (BIAS) {
            if (i > 0 && j > 0) {
                int pi = i - 1, pj = j - 1;
                int dy = pi / 7 - pj / 7 + 6;
                int dx = pi % 7 - pj % 7 + 6;
                s += rel_pos[head * 169 + dy * 13 + dx];
            }
        }
        S[i][j] = s;
    }
    __syncthreads();

    int lane = tid & 31, wp = tid >> 5;
    for (int i = wp; i < N; i += 8) {
        float m = -1e30f;
        for (int j = lane; j < N; j += 32) m = fmaxf(m, S[i][j]);
        #pragma unroll
        for (int o = 16; o; o >>= 1) m = fmaxf(m, __shfl_xor_sync(0xffffffffu, m, o));
        float sum = 0.f;
        for (int j = lane; j < N; j += 32) {
            float e = __expf(S[i][j] - m);
            S[i][j] = e;
            sum += e;
        }
        #pragma unroll
        for (int o = 16; o; o >>= 1) sum += __shfl_xor_sync(0xffffffffu, sum, o);
        float inv = 1.0f / sum;
        for (int j = lane; j < N; j += 32) S[i][j] *= inv;
    }
    __syncthreads();

    for (int idx = tid; idx < N * HDIM; idx += 256) {
        int i = idx >> 5, d = idx & 31;
        float o = 0.f;
        for (int j = 0; j < N; j++) o = fmaf(S[i][j], Vs[j][d], o);
        out[((size_t)win * N + i) * CDIM + head * 32 + d] = o;
    }
}

// ---------------------------------------------------------------------------
// Scatter final tokens to (cls_out, patch_out) in NCHW
// ---------------------------------------------------------------------------
__global__ void scatter_out_kernel(const float* __restrict__ F,
                                   float* __restrict__ out) {
    size_t idx = (size_t)blockIdx.x * 256 + threadIdx.x;
    const size_t total = CLS_OUT_SZ + PATCH_OUT_SZ;
    if (idx >= total) return;
    if (idx < CLS_OUT_SZ) {
        int wv = idx & 63;
        int c  = (int)((idx >> 6) & 255);
        int b  = (int)(idx >> 14);
        out[idx] = F[((size_t)(b * 64 + wv) * NTOK) * CDIM + c];
    } else {
        size_t p = idx - CLS_OUT_SZ;
        int x = (int)(p % 56);
        int y = (int)((p / 56) % 56);
        int c = (int)((p / (56 * 56)) & 255);
        int b = (int)(p / ((size_t)56 * 56 * 256));
        int wy = y / 7, iy = y - wy * 7;
        int wx = x / 7, ix = x - wx * 7;
        size_t row = (size_t)(b * 64 + wy * 8 + wx) * NTOK + 1 + iy * 7 + ix;
        out[idx] = F[row * CDIM + c];
    }
}

// ---------------------------------------------------------------------------
// Launch sequence
// ---------------------------------------------------------------------------
extern "C" void kernel_launch(void* const* d_in, const int* in_sizes, int n_in,
                              void* d_out, int out_size)
{
    const float* cls    = (const float*)d_in[0];
    const float* patch  = (const float*)d_in[1];
    const float* n0w = (const float*)d_in[2], *n0b = (const float*)d_in[3];
    const float* n1w = (const float*)d_in[4], *n1b = (const float*)d_in[5];
    const float* n2w = (const float*)d_in[6], *n2b = (const float*)d_in[7];
    const float* qkvw  = (const float*)d_in[8];
    const float* projw = (const float*)d_in[9], *projb = (const float*)d_in[10];
    const float* relp  = (const float*)d_in[11];
    const float* fc1w  = (const float*)d_in[12], *fc1b = (const float*)d_in[13];
    const float* fc2w  = (const float*)d_in[14], *fc2b = (const float*)d_in[15];
    float* out = (float*)d_out;

    float* pool;
    cudaGetSymbolAddress((void**)&pool, g_pool);
    float* X       = pool + X_OFF;
    float* Xln     = pool + XLN_OFF;
    float* QKV     = pool + QKV_OFF;
    float* TMP     = pool + TMP_OFF;
    float* Hb      = pool + H_OFF;
    float* clsflat = pool + CLSFLAT_OFF;
    float* clsln   = pool + CLSLN_OFF;
    float* clsqkv  = pool + CLSQKV_OFF;
    float* clsattn = pool + CLSATT_OFF;
    float* ATT = Xln;
    float* F   = Xln;

    const unsigned MB = (unsigned)(TOK_TOTAL / 128);   // 800

    // ---- cls-token path
    cls_ln_kernel<<<NWIN, 256>>>(cls, n0w, n0b, clsflat, clsln);
    tf32gemm_nt<<<dim3(6, 16), 256>>>(clsln, qkvw, clsqkv, nullptr, nullptr,
                                      NWIN, 768, 256, 256, 256, 768, 0);
    attn_kernel<64, false><<<BATCH * NHEAD, 256>>>(clsqkv, nullptr, clsattn);
    tf32gemm_nt<<<dim3(2, 16), 256>>>(clsattn, projw, X, projb, clsflat,
                                      NWIN, 256, 256, 256, 256, NTOK * CDIM, 1);

    // ---- windowed attention block
    {
        size_t n = (size_t)NWIN * 49 * CDIM;
        gather_patch_kernel<<<(unsigned)((n + 255) / 256), 256>>>(patch, X);
    }
    ln_kernel<<<(unsigned)TOK_TOTAL, 256>>>(X, n1w, n1b, Xln);
    tf32gemm_nt<<<dim3(6, MB), 256>>>(Xln, qkvw, QKV, nullptr, nullptr,
                                      (int)TOK_TOTAL, 768, 256, 256, 256, 768, 0);
    attn_kernel<NTOK, true><<<NWIN * NHEAD, 256>>>(QKV, relp, ATT);
    tf32gemm_nt<<<dim3(2, MB), 256>>>(ATT, projw, TMP, projb, X,
                                      (int)TOK_TOTAL, 256, 256, 256, 256, 256, 1);

    // ---- MLP block: LN2 -> (fc1 chunk -> GELU -> fc2 partial) x2
    ln_kernel<<<(unsigned)TOK_TOTAL, 256>>>(TMP, n2w, n2b, X);
    tf32gemm_nt<<<dim3(4, MB), 256>>>(X, fc1w, Hb, fc1b, nullptr,
                                      (int)TOK_TOTAL, 512, 256, 256, 256, 512, 2);
    tf32gemm_nt<<<dim3(2, MB), 256>>>(Hb, fc2w, F, fc2b, TMP,
                                      (int)TOK_TOTAL, 256, 512, 512, HIDD, 256, 1);
    tf32gemm_nt<<<dim3(4, MB), 256>>>(X, fc1w + 512 * 256, Hb, fc1b + 512, nullptr,
                                      (int)TOK_TOTAL, 512, 256, 256, 256, 512, 2);
    tf32gemm_nt<<<dim3(2, MB), 256>>>(Hb, fc2w + 512, F, nullptr, F,
                                      (int)TOK_TOTAL, 256, 512, 512, HIDD, 256, 1);

    // ---- outputs
    {
        size_t n = CLS_OUT_SZ + PATCH_OUT_SZ;
        scatter_out_kernel<<<(unsigned)((n + 255) / 256), 256>>>(F, out);
    }
}